// round 3
// baseline (speedup 1.0000x reference)
#include <cuda_runtime.h>
#include <cuda_bf16.h>

// Problem constants
#define NXv 128
#define NYv 128
#define NZv 8
#define NVOX (NXv * NYv * NZv)   // 131072
#define NVIEW 6
#define NCH 64
#define HFv 116
#define WFv 200
#define FEAT_HW (HFv * WFv)      // 23200
#define IMG_W 1600.0f
#define IMG_H 928.0f

// Channel-last scratch: [V, HF, WF, C]  (35.6 MB)
__device__ __align__(256) static float g_feat_t[NVIEW * FEAT_HW * NCH];

// ---------------------------------------------------------------------------
// Kernel 1: transpose [V,C,H,W] -> [V,H,W,C] with shared-memory tiles.
// block = (32,8); tile = 32(c) x 32(w); grid = (w_tiles=7, c_tiles=2, v*h=696)
// ---------------------------------------------------------------------------
__global__ __launch_bounds__(256)
void transpose_kernel(const float* __restrict__ xfov)
{
    __shared__ float tile[32][33];

    const int w_tile = blockIdx.x;        // 0..6
    const int c_tile = blockIdx.y;        // 0..1
    const int vh     = blockIdx.z;        // 0..695
    const int v      = vh / HFv;
    const int h      = vh - v * HFv;

    const int tx = threadIdx.x;           // 0..31
    const int ty = threadIdx.y;           // 0..7

    // Read: coalesced along w
    {
        const int w = w_tile * 32 + tx;
#pragma unroll
        for (int i = 0; i < 4; i++) {
            const int c = c_tile * 32 + ty + i * 8;
            if (w < WFv) {
                tile[ty + i * 8][tx] =
                    xfov[((size_t)(v * NCH + c) * HFv + h) * WFv + w];
            }
        }
    }
    __syncthreads();

    // Write: coalesced along c
    {
        const int c = c_tile * 32 + tx;
#pragma unroll
        for (int i = 0; i < 4; i++) {
            const int w = w_tile * 32 + ty + i * 8;
            if (w < WFv) {
                g_feat_t[((size_t)(v * FEAT_HW + h * WFv + w)) * NCH + c] =
                    tile[tx][ty + i * 8];
            }
        }
    }
}

// ---------------------------------------------------------------------------
// Kernel 2: gather. 2 threads per point, 32 channels each.
// Channel-last layout => each tap = 8 contiguous LDG.128 per thread.
// ---------------------------------------------------------------------------
__global__ __launch_bounds__(256)
void gather_kernel(const float* __restrict__ points,
                   const float* __restrict__ proj,
                   float* __restrict__ out)
{
    __shared__ float sM[NVIEW * 16];
    if (threadIdx.x < NVIEW * 16) sM[threadIdx.x] = proj[threadIdx.x];
    __syncthreads();

    const int t    = blockIdx.x * blockDim.x + threadIdx.x; // 0..262143
    const int p    = t >> 1;                                // voxel (output-linear)
    const int half = t & 1;                                 // channel half

    // Output-linear p -> (x,y,z); point index n = z*NY*NX + y*NX + x
    const int z = p & (NZv - 1);
    const int y = (p >> 3) & (NYv - 1);
    const int x = p >> 10;
    const int n = (z * NYv + y) * NXv + x;

    const float pxw = points[n * 3 + 0];
    const float pyw = points[n * 3 + 1];
    const float pzw = points[n * 3 + 2];

    float4 acc[8];
#pragma unroll
    for (int i = 0; i < 8; i++) acc[i] = make_float4(0.f, 0.f, 0.f, 0.f);
    int cnt = 0;

#pragma unroll 1
    for (int v = 0; v < NVIEW; v++) {
        const float* M = &sM[v * 16];
        const float cx = M[0] * pxw + M[1] * pyw + M[2]  * pzw + M[3];
        const float cy = M[4] * pxw + M[5] * pyw + M[6]  * pzw + M[7];
        const float d  = M[8] * pxw + M[9] * pyw + M[10] * pzw + M[11];

        const float ds = (fabsf(d) > 1e-6f) ? d : 1e-6f;
        const float u  = cx / ds;
        const float vv = cy / ds;

        const bool valid = (d > 0.0f) & (u > 0.0f) & (u < IMG_W)
                                      & (vv > 0.0f) & (vv < IMG_H);
        if (!valid) continue;

        const float fx = u  * ((float)WFv / IMG_W) - 0.5f;
        const float fy = vv * ((float)HFv / IMG_H) - 0.5f;
        const float x0f = floorf(fx);
        const float y0f = floorf(fy);
        const int x0 = (int)x0f;
        const int y0 = (int)y0f;
        const float wx1 = fx - x0f;
        const float wy1 = fy - y0f;
        const float wx0 = 1.0f - wx1;
        const float wy0 = 1.0f - wy1;

        const bool xi0 = (x0 >= 0) & (x0 < WFv);
        const bool xi1 = (x0 + 1 >= 0) & (x0 + 1 < WFv);
        const bool yi0 = (y0 >= 0) & (y0 < HFv);
        const bool yi1 = (y0 + 1 >= 0) & (y0 + 1 < HFv);

        const int xc0 = min(max(x0, 0), WFv - 1);
        const int xc1 = min(max(x0 + 1, 0), WFv - 1);
        const int yc0 = min(max(y0, 0), HFv - 1);
        const int yc1 = min(max(y0 + 1, 0), HFv - 1);

        const float w00 = wx0 * wy0 * (float)(xi0 & yi0);
        const float w10 = wx1 * wy0 * (float)(xi1 & yi0);
        const float w01 = wx0 * wy1 * (float)(xi0 & yi1);
        const float w11 = wx1 * wy1 * (float)(xi1 & yi1);

        const size_t vbase = (size_t)v * FEAT_HW;
        const float4* t00 = (const float4*)(g_feat_t + ((vbase + (size_t)yc0 * WFv + xc0) * NCH + half * 32));
        const float4* t10 = (const float4*)(g_feat_t + ((vbase + (size_t)yc0 * WFv + xc1) * NCH + half * 32));
        const float4* t01 = (const float4*)(g_feat_t + ((vbase + (size_t)yc1 * WFv + xc0) * NCH + half * 32));
        const float4* t11 = (const float4*)(g_feat_t + ((vbase + (size_t)yc1 * WFv + xc1) * NCH + half * 32));

#pragma unroll
        for (int i = 0; i < 8; i++) {
            const float4 f00 = __ldg(t00 + i);
            const float4 f10 = __ldg(t10 + i);
            const float4 f01 = __ldg(t01 + i);
            const float4 f11 = __ldg(t11 + i);
            acc[i].x += w00 * f00.x + w10 * f10.x + w01 * f01.x + w11 * f11.x;
            acc[i].y += w00 * f00.y + w10 * f10.y + w01 * f01.y + w11 * f11.y;
            acc[i].z += w00 * f00.z + w10 * f10.z + w01 * f01.z + w11 * f11.z;
            acc[i].w += w00 * f00.w + w10 * f10.w + w01 * f01.w + w11 * f11.w;
        }
        cnt++;
    }

    const float inv = (cnt > 0) ? (1.0f / (float)cnt) : 0.0f;
    const int cbase = half * 32;
#pragma unroll
    for (int i = 0; i < 8; i++) {
        out[(size_t)(cbase + i * 4 + 0) * NVOX + p] = acc[i].x * inv;
        out[(size_t)(cbase + i * 4 + 1) * NVOX + p] = acc[i].y * inv;
        out[(size_t)(cbase + i * 4 + 2) * NVOX + p] = acc[i].z * inv;
        out[(size_t)(cbase + i * 4 + 3) * NVOX + p] = acc[i].w * inv;
    }
}

extern "C" void kernel_launch(void* const* d_in, const int* in_sizes, int n_in,
                              void* d_out, int out_size)
{
    const float* x_fov  = (const float*)d_in[0];  // [1,6,64,116,200]
    const float* points = (const float*)d_in[1];  // [131072,3]
    const float* proj   = (const float*)d_in[2];  // [6,4,4]
    float* out = (float*)d_out;                   // [1,64,128,128,8]

    // Transpose features to channel-last
    {
        dim3 blk(32, 8);
        dim3 grd((WFv + 31) / 32, NCH / 32, NVIEW * HFv);
        transpose_kernel<<<grd, blk>>>(x_fov);
    }

    // Gather: 2 threads per point
    {
        const int threads = 256;
        const int blocks  = (NVOX * 2) / threads;  // 1024
        gather_kernel<<<blocks, threads>>>(points, proj, out);
    }
}

// round 4
// speedup vs baseline: 2.0140x; 2.0140x over previous
#include <cuda_runtime.h>
#include <cuda_fp16.h>

// Problem constants
#define NXv 128
#define NYv 128
#define NZv 8
#define NVOX (NXv * NYv * NZv)   // 131072
#define NVIEW 6
#define NCH 64
#define HFv 116
#define WFv 200
#define FEAT_HW (HFv * WFv)      // 23200
#define IMG_W 1600.0f
#define IMG_H 928.0f

// Channel-last fp16 scratch: [V, HF, WF, C]  (17.8 MB). One tap = 128B line.
__device__ __align__(256) static __half g_feat_h[NVIEW * FEAT_HW * NCH];

// ---------------------------------------------------------------------------
// Kernel 1: transpose+convert [V,C,H,W] fp32 -> [V,H,W,C] fp16.
// Block: 256 threads handles a (64c x 32w) tile of one (v,h) row.
// Writes: 32 lanes emit one half2 each -> one 128B line per instruction.
// ---------------------------------------------------------------------------
__global__ __launch_bounds__(256)
void convert_kernel(const float* __restrict__ xfov)
{
    __shared__ float tile[NCH][33];

    const int w0 = blockIdx.x * 32;
    const int vh = blockIdx.y;            // 0..695
    const int v  = vh / HFv;
    const int h  = vh - v * HFv;

    const int tx = threadIdx.x & 31;
    const int ty = threadIdx.x >> 5;      // 0..7

    // Read: coalesced along w (128B per row-read)
    const int w = w0 + tx;
    if (w < WFv) {
#pragma unroll
        for (int i = 0; i < 8; i++) {
            const int c = ty + i * 8;
            tile[c][tx] = xfov[((size_t)(v * NCH + c) * HFv + h) * WFv + w];
        }
    }
    __syncthreads();

    // Write: for each w in tile, 32 lanes write half2 (c=2tx,2tx+1) -> 128B line
    __half2* dst = (__half2*)g_feat_h;
#pragma unroll
    for (int j = 0; j < 4; j++) {
        const int ww = w0 + ty + 8 * j;
        if (ww < WFv) {
            const float a = tile[2 * tx + 0][ty + 8 * j];
            const float b = tile[2 * tx + 1][ty + 8 * j];
            dst[(size_t)(v * FEAT_HW + h * WFv + ww) * (NCH / 2) + tx] =
                __floats2half2_rn(a, b);
        }
    }
}

// ---------------------------------------------------------------------------
// Kernel 2: gather. 4 threads per point, 16 channels each.
// Each tap: 2x LDG.128 of fp16 -> warp touches only 8 lines per instruction.
// ---------------------------------------------------------------------------
__device__ __forceinline__ void fma8(float* acc, uint4 a, float w)
{
    const __half2* h = (const __half2*)&a;
#pragma unroll
    for (int k = 0; k < 4; k++) {
        const float2 f = __half22float2(h[k]);
        acc[2 * k + 0] += w * f.x;
        acc[2 * k + 1] += w * f.y;
    }
}

__global__ __launch_bounds__(256)
void gather_kernel(const float* __restrict__ points,
                   const float* __restrict__ proj,
                   float* __restrict__ out)
{
    __shared__ float sM[NVIEW * 16];
    if (threadIdx.x < NVIEW * 16) sM[threadIdx.x] = proj[threadIdx.x];
    __syncthreads();

    const int t = blockIdx.x * blockDim.x + threadIdx.x; // 0..524287
    const int p = t >> 2;                                // voxel (output-linear)
    const int q = t & 3;                                 // channel quarter

    const int z = p & (NZv - 1);
    const int y = (p >> 3) & (NYv - 1);
    const int x = p >> 10;
    const int n = (z * NYv + y) * NXv + x;

    const float pxw = points[n * 3 + 0];
    const float pyw = points[n * 3 + 1];
    const float pzw = points[n * 3 + 2];

    float acc[16];
#pragma unroll
    for (int i = 0; i < 16; i++) acc[i] = 0.0f;
    int cnt = 0;

#pragma unroll 1
    for (int v = 0; v < NVIEW; v++) {
        const float* M = &sM[v * 16];
        const float cx = M[0] * pxw + M[1] * pyw + M[2]  * pzw + M[3];
        const float cy = M[4] * pxw + M[5] * pyw + M[6]  * pzw + M[7];
        const float d  = M[8] * pxw + M[9] * pyw + M[10] * pzw + M[11];

        const float ds = (fabsf(d) > 1e-6f) ? d : 1e-6f;
        const float u  = cx / ds;
        const float vv = cy / ds;

        const bool valid = (d > 0.0f) & (u > 0.0f) & (u < IMG_W)
                                      & (vv > 0.0f) & (vv < IMG_H);
        if (!valid) continue;

        const float fx = u  * ((float)WFv / IMG_W) - 0.5f;
        const float fy = vv * ((float)HFv / IMG_H) - 0.5f;
        const float x0f = floorf(fx);
        const float y0f = floorf(fy);
        const int x0 = (int)x0f;
        const int y0 = (int)y0f;
        const float wx1 = fx - x0f;
        const float wy1 = fy - y0f;
        const float wx0 = 1.0f - wx1;
        const float wy0 = 1.0f - wy1;

        const bool xi0 = (x0 >= 0) & (x0 < WFv);
        const bool xi1 = (x0 + 1 >= 0) & (x0 + 1 < WFv);
        const bool yi0 = (y0 >= 0) & (y0 < HFv);
        const bool yi1 = (y0 + 1 >= 0) & (y0 + 1 < HFv);

        const int xc0 = min(max(x0, 0), WFv - 1);
        const int xc1 = min(max(x0 + 1, 0), WFv - 1);
        const int yc0 = min(max(y0, 0), HFv - 1);
        const int yc1 = min(max(y0 + 1, 0), HFv - 1);

        const float w00 = wx0 * wy0 * (float)(xi0 & yi0);
        const float w10 = wx1 * wy0 * (float)(xi1 & yi0);
        const float w01 = wx0 * wy1 * (float)(xi0 & yi1);
        const float w11 = wx1 * wy1 * (float)(xi1 & yi1);

        const size_t vbase = (size_t)v * FEAT_HW;
        const int coff = q * 16;  // in halves

        const uint4* t00 = (const uint4*)(g_feat_h + ((vbase + (size_t)yc0 * WFv + xc0) * NCH + coff));
        const uint4* t10 = (const uint4*)(g_feat_h + ((vbase + (size_t)yc0 * WFv + xc1) * NCH + coff));
        const uint4* t01 = (const uint4*)(g_feat_h + ((vbase + (size_t)yc1 * WFv + xc0) * NCH + coff));
        const uint4* t11 = (const uint4*)(g_feat_h + ((vbase + (size_t)yc1 * WFv + xc1) * NCH + coff));

        const uint4 a00 = __ldg(t00 + 0), b00 = __ldg(t00 + 1);
        const uint4 a10 = __ldg(t10 + 0), b10 = __ldg(t10 + 1);
        const uint4 a01 = __ldg(t01 + 0), b01 = __ldg(t01 + 1);
        const uint4 a11 = __ldg(t11 + 0), b11 = __ldg(t11 + 1);

        fma8(acc + 0, a00, w00);  fma8(acc + 8, b00, w00);
        fma8(acc + 0, a10, w10);  fma8(acc + 8, b10, w10);
        fma8(acc + 0, a01, w01);  fma8(acc + 8, b01, w01);
        fma8(acc + 0, a11, w11);  fma8(acc + 8, b11, w11);
        cnt++;
    }

    const float inv = (cnt > 0) ? (1.0f / (float)cnt) : 0.0f;
    const int cbase = q * 16;
#pragma unroll
    for (int j = 0; j < 16; j++) {
        out[(size_t)(cbase + j) * NVOX + p] = acc[j] * inv;
    }
}

extern "C" void kernel_launch(void* const* d_in, const int* in_sizes, int n_in,
                              void* d_out, int out_size)
{
    const float* x_fov  = (const float*)d_in[0];  // [1,6,64,116,200]
    const float* points = (const float*)d_in[1];  // [131072,3]
    const float* proj   = (const float*)d_in[2];  // [6,4,4]
    float* out = (float*)d_out;                   // [1,64,128,128,8]

    // Transpose + fp16 convert
    {
        dim3 blk(256);
        dim3 grd((WFv + 31) / 32, NVIEW * HFv);   // (7, 696)
        convert_kernel<<<grd, blk>>>(x_fov);
    }

    // Gather: 4 threads per point
    {
        const int threads = 256;
        const int blocks  = (NVOX * 4) / threads; // 2048
        gather_kernel<<<blocks, threads>>>(points, proj, out);
    }
}

// round 5
// speedup vs baseline: 2.4613x; 1.2221x over previous
#include <cuda_runtime.h>
#include <cuda_fp16.h>

// Problem constants
#define NXv 128
#define NYv 128
#define NZv 8
#define NVOX (NXv * NYv * NZv)   // 131072
#define NVIEW 6
#define NCH 64
#define HFv 116
#define WFv 200
#define FEAT_HW (HFv * WFv)      // 23200
#define IMG_W 1600.0f
#define IMG_H 928.0f

// Channel-last fp16 scratch: [V, HF, WF, C]  (17.8 MB). One tap = 128B line.
__device__ __align__(256) static __half g_feat_h[NVIEW * FEAT_HW * NCH];

// ---------------------------------------------------------------------------
// Kernel 1: transpose+convert [V,C,H,W] fp32 -> [V,H,W,C] fp16.
// ---------------------------------------------------------------------------
__global__ __launch_bounds__(256)
void convert_kernel(const float* __restrict__ xfov)
{
    __shared__ float tile[NCH][33];

    const int w0 = blockIdx.x * 32;
    const int vh = blockIdx.y;            // 0..695
    const int v  = vh / HFv;
    const int h  = vh - v * HFv;

    const int tx = threadIdx.x & 31;
    const int ty = threadIdx.x >> 5;      // 0..7

    const int w = w0 + tx;
    if (w < WFv) {
#pragma unroll
        for (int i = 0; i < 8; i++) {
            const int c = ty + i * 8;
            tile[c][tx] = xfov[((size_t)(v * NCH + c) * HFv + h) * WFv + w];
        }
    }
    __syncthreads();

    __half2* dst = (__half2*)g_feat_h;
#pragma unroll
    for (int j = 0; j < 4; j++) {
        const int ww = w0 + ty + 8 * j;
        if (ww < WFv) {
            const float a = tile[2 * tx + 0][ty + 8 * j];
            const float b = tile[2 * tx + 1][ty + 8 * j];
            dst[(size_t)(v * FEAT_HW + h * WFv + ww) * (NCH / 2) + tx] =
                __floats2half2_rn(a, b);
        }
    }
}

// ---------------------------------------------------------------------------
// Kernel 2: gather. 4 threads per point, 16 channels each.
// Tap combine in packed fp16 (HMUL2/HFMA2); cross-view accumulate in fp32.
// ---------------------------------------------------------------------------
__device__ __forceinline__ void hcomb(float* acc,
                                      const uint4& a00, const uint4& a10,
                                      const uint4& a01, const uint4& a11,
                                      __half2 w00, __half2 w10,
                                      __half2 w01, __half2 w11)
{
    const __half2* f00 = (const __half2*)&a00;
    const __half2* f10 = (const __half2*)&a10;
    const __half2* f01 = (const __half2*)&a01;
    const __half2* f11 = (const __half2*)&a11;
#pragma unroll
    for (int k = 0; k < 4; k++) {
        __half2 s = __hmul2(f00[k], w00);
        s = __hfma2(f10[k], w10, s);
        s = __hfma2(f01[k], w01, s);
        s = __hfma2(f11[k], w11, s);
        const float2 sf = __half22float2(s);
        acc[2 * k + 0] += sf.x;
        acc[2 * k + 1] += sf.y;
    }
}

__global__ __launch_bounds__(256)
void gather_kernel(const float* __restrict__ points,
                   const float* __restrict__ proj,
                   float* __restrict__ out)
{
    __shared__ float sM[NVIEW * 16];
    if (threadIdx.x < NVIEW * 16) sM[threadIdx.x] = proj[threadIdx.x];
    __syncthreads();

    const int t = blockIdx.x * blockDim.x + threadIdx.x; // 0..524287
    const int p = t >> 2;                                // voxel (output-linear)
    const int q = t & 3;                                 // channel quarter

    const int z = p & (NZv - 1);
    const int y = (p >> 3) & (NYv - 1);
    const int x = p >> 10;
    const int n = (z * NYv + y) * NXv + x;

    const float pxw = points[n * 3 + 0];
    const float pyw = points[n * 3 + 1];
    const float pzw = points[n * 3 + 2];

    float acc[16];
#pragma unroll
    for (int i = 0; i < 16; i++) acc[i] = 0.0f;
    int cnt = 0;

#pragma unroll 1
    for (int v = 0; v < NVIEW; v++) {
        const float* M = &sM[v * 16];
        const float cx = fmaf(M[0], pxw, fmaf(M[1], pyw, fmaf(M[2],  pzw, M[3])));
        const float cy = fmaf(M[4], pxw, fmaf(M[5], pyw, fmaf(M[6],  pzw, M[7])));
        const float d  = fmaf(M[8], pxw, fmaf(M[9], pyw, fmaf(M[10], pzw, M[11])));

        const float ds = (fabsf(d) > 1e-6f) ? d : 1e-6f;
        const float r  = __fdividef(1.0f, ds);
        const float u  = cx * r;
        const float vv = cy * r;

        const bool valid = (d > 0.0f) & (u > 0.0f) & (u < IMG_W)
                                      & (vv > 0.0f) & (vv < IMG_H);
        if (!valid) continue;

        // Exact power-of-2 scale: WF/IMG_W = HF/IMG_H = 0.125
        const float fx = fmaf(u,  0.125f, -0.5f);
        const float fy = fmaf(vv, 0.125f, -0.5f);
        const float x0f = floorf(fx);
        const float y0f = floorf(fy);
        const int x0 = (int)x0f;   // in [-1, 199]
        const int y0 = (int)y0f;   // in [-1, 115]
        const float wx1 = fx - x0f;
        const float wy1 = fy - y0f;

        // Zero out-of-range tap weights via FSEL (only edges can be OOB)
        const float wxl = (x0 >= 0)       ? (1.0f - wx1) : 0.0f;
        const float wxr = (x0 < WFv - 1)  ? wx1          : 0.0f;
        const float wyt = (y0 >= 0)       ? (1.0f - wy1) : 0.0f;
        const float wyb = (y0 < HFv - 1)  ? wy1          : 0.0f;

        const int xc0 = max(x0, 0);
        const int xc1 = min(x0 + 1, WFv - 1);
        const int yc0 = max(y0, 0);
        const int yc1 = min(y0 + 1, HFv - 1);

        const __half2 hw00 = __float2half2_rn(wxl * wyt);
        const __half2 hw10 = __float2half2_rn(wxr * wyt);
        const __half2 hw01 = __float2half2_rn(wxl * wyb);
        const __half2 hw11 = __float2half2_rn(wxr * wyb);

        const size_t vbase = (size_t)v * FEAT_HW;
        const int coff = q * 16;  // in halves

        const uint4* t00 = (const uint4*)(g_feat_h + ((vbase + (size_t)yc0 * WFv + xc0) * NCH + coff));
        const uint4* t10 = (const uint4*)(g_feat_h + ((vbase + (size_t)yc0 * WFv + xc1) * NCH + coff));
        const uint4* t01 = (const uint4*)(g_feat_h + ((vbase + (size_t)yc1 * WFv + xc0) * NCH + coff));
        const uint4* t11 = (const uint4*)(g_feat_h + ((vbase + (size_t)yc1 * WFv + xc1) * NCH + coff));

        const uint4 a00 = __ldg(t00 + 0), b00 = __ldg(t00 + 1);
        const uint4 a10 = __ldg(t10 + 0), b10 = __ldg(t10 + 1);
        const uint4 a01 = __ldg(t01 + 0), b01 = __ldg(t01 + 1);
        const uint4 a11 = __ldg(t11 + 0), b11 = __ldg(t11 + 1);

        hcomb(acc + 0, a00, a10, a01, a11, hw00, hw10, hw01, hw11);
        hcomb(acc + 8, b00, b10, b01, b11, hw00, hw10, hw01, hw11);
        cnt++;
    }

    const float inv = (cnt > 0) ? (1.0f / (float)cnt) : 0.0f;
    const int cbase = q * 16;
#pragma unroll
    for (int j = 0; j < 16; j++) {
        out[(size_t)(cbase + j) * NVOX + p] = acc[j] * inv;
    }
}

extern "C" void kernel_launch(void* const* d_in, const int* in_sizes, int n_in,
                              void* d_out, int out_size)
{
    const float* x_fov  = (const float*)d_in[0];  // [1,6,64,116,200]
    const float* points = (const float*)d_in[1];  // [131072,3]
    const float* proj   = (const float*)d_in[2];  // [6,4,4]
    float* out = (float*)d_out;                   // [1,64,128,128,8]

    {
        dim3 blk(256);
        dim3 grd((WFv + 31) / 32, NVIEW * HFv);   // (7, 696)
        convert_kernel<<<grd, blk>>>(x_fov);
    }
    {
        const int threads = 256;
        const int blocks  = (NVOX * 4) / threads; // 2048
        gather_kernel<<<blocks, threads>>>(points, proj, out);
    }
}